// round 6
// baseline (speedup 1.0000x reference)
#include <cuda_runtime.h>
#include <cstdint>
#include <cfloat>

#define NDOMS   262144
#define NPULSES 4194304
#define EMBED   64

// ---- static scratch (no allocs allowed) ----
__device__ int   g_count [NDOMS];
__device__ int   g_offset[NDOMS];
__device__ int   g_cursor[NDOMS];
__device__ int   g_perm  [NPULSES];
__device__ int   g_bsum  [256];
__device__ int   g_is64;
// W re-paired for f32x2: g_wp[kp*128 + 2*j + lo] = W[j*128 + 2*kp + lo]
// viewed as ull: Wu[kp*64 + j] = ( W[j][2kp], W[j][2kp+1] )
__device__ float g_wp[128 * 64];

// ---- f32x2 packed helpers ----
__device__ __forceinline__ void unpack2(unsigned long long u, float& x, float& y) {
    asm("mov.b64 {%0, %1}, %2;" : "=f"(x), "=f"(y) : "l"(u));
}
__device__ __forceinline__ void ffma2(unsigned long long& acc,
                                      unsigned long long a, unsigned long long b) {
    asm("fma.rn.f32x2 %0, %1, %2, %0;" : "+l"(acc) : "l"(a), "l"(b));
}

// ---------------------------------------------------------------- idx dtype probe
__global__ void k_detect(const unsigned int* __restrict__ idx32) {
    int is64 = 1;
    for (int i = 0; i < 128; i++)
        if (idx32[2 * i + 1] != 0u) { is64 = 0; break; }
    g_is64 = is64;
}

__device__ __forceinline__ int load_idx(const void* __restrict__ idx, int i) {
    if (g_is64) return (int)((const long long*)idx)[i];
    return ((const int*)idx)[i];
}

// ---------------------------------------------------------------- zero counts
__global__ void k_zero() {
    int i = blockIdx.x * 1024 + threadIdx.x;
    g_count[i] = 0;
}

// ---------------------------------------------------------------- W pair-repack
__global__ void k_wt(const float* __restrict__ W) {
    int s = blockIdx.x * 256 + threadIdx.x;      // 8192 threads
    int j = s >> 7, k = s & 127;
    g_wp[(k >> 1) * 128 + 2 * j + (k & 1)] = W[s];
}

// ---------------------------------------------------------------- histogram
__global__ void k_hist(const void* __restrict__ idx, int n) {
    int i = blockIdx.x * 256 + threadIdx.x;
    if (i < n) atomicAdd(&g_count[load_idx(idx, i)], 1);
}

// ---------------------------------------------------------------- scan (3 phases)
__global__ void k_scan1() {
    __shared__ int sh[1024];
    int t = threadIdx.x;
    int i = blockIdx.x * 1024 + t;
    int v = g_count[i];
    sh[t] = v;
    __syncthreads();
    for (int off = 1; off < 1024; off <<= 1) {
        int add = (t >= off) ? sh[t - off] : 0;
        __syncthreads();
        sh[t] += add;
        __syncthreads();
    }
    g_offset[i] = sh[t] - v;
    if (t == 1023) g_bsum[blockIdx.x] = sh[t];
}

__global__ void k_scan2() {
    __shared__ int sh[256];
    int t = threadIdx.x;
    int v = g_bsum[t];
    sh[t] = v;
    __syncthreads();
    for (int off = 1; off < 256; off <<= 1) {
        int add = (t >= off) ? sh[t - off] : 0;
        __syncthreads();
        sh[t] += add;
        __syncthreads();
    }
    g_bsum[t] = sh[t] - v;
}

__global__ void k_scan3() {
    int t = threadIdx.x;
    int i = blockIdx.x * 1024 + t;
    int o = g_offset[i] + g_bsum[blockIdx.x];
    g_offset[i] = o;
    g_cursor[i] = o;
}

// ---------------------------------------------------------------- scatter pulse ids
__global__ void k_scatter(const void* __restrict__ idx, int n) {
    int i = blockIdx.x * 256 + threadIdx.x;
    if (i < n) {
        int d   = load_idx(idx, i);
        int pos = atomicAdd(&g_cursor[d], 1);
        g_perm[pos] = i;
    }
}

// ---------------------------------------------------------------- fused pool+proj
// Persistent. Warp per dom: gather rows (MLP=8), pool in regs, stage concat
// row in smem (own-warp only -> __syncwarp), then projection epilogue:
// even/odd-k partial sums per j via fma.rn.f32x2 (no packing MOVs).
// out[dom][j] = sum_k concat[k]*W[j][k] + b[j]
#define PGRID 740   // 148 SMs * 5 (reg-limited occupancy @256 thr)

__global__ void __launch_bounds__(256) k_pool_gemm(const float* __restrict__ emb,
                                                   const float* __restrict__ bias,
                                                   float* __restrict__ out) {
    __shared__ float Wsm[128 * 64];     // paired W, 32KB
    __shared__ float Csm[8][128];       // concat row per warp, 4KB

    int tid = threadIdx.x, wid = tid >> 5, lane = tid & 31;

    // stage paired W once per block
    const float4* Wp4 = (const float4*)g_wp;
    float4* Ws4 = (float4*)Wsm;
    #pragma unroll
    for (int i = 0; i < 8; i++)
        Ws4[tid + i * 256] = Wp4[tid + i * 256];
    float b0 = bias[lane], b1 = bias[lane + 32];
    __syncthreads();

    const float2* e2 = (const float2*)emb;
    const unsigned long long* Wu = (const unsigned long long*)Wsm;  // [kp][j]
    const unsigned long long* Au = (const unsigned long long*)Csm[wid];
    float2* crow = (float2*)Csm[wid];

    for (int grp = blockIdx.x; grp < NDOMS / 8; grp += PGRID) {
        int dom   = grp * 8 + wid;
        int start = g_offset[dom];
        int cnt   = g_count[dom];

        float sx = 0.f, sy = 0.f;
        float mx = -FLT_MAX, my = -FLT_MAX;

        int i = 0;
        int p[8];
        if (cnt >= 8) {
            #pragma unroll
            for (int u = 0; u < 8; u++) p[u] = g_perm[start + u];
        }
        while (i + 8 <= cnt) {
            float2 v[8];
            #pragma unroll
            for (int u = 0; u < 8; u++)
                v[u] = e2[(size_t)p[u] * 32 + lane];
            i += 8;
            if (i + 8 <= cnt) {
                #pragma unroll
                for (int u = 0; u < 8; u++) p[u] = g_perm[start + i + u];
            }
            #pragma unroll
            for (int u = 0; u < 8; u++) {
                sx += v[u].x; sy += v[u].y;
                mx = fmaxf(mx, v[u].x); my = fmaxf(my, v[u].y);
            }
        }
        for (; i < cnt; i++) {
            int q = g_perm[start + i];
            float2 v = e2[(size_t)q * 32 + lane];
            sx += v.x; sy += v.y;
            mx = fmaxf(mx, v.x); my = fmaxf(my, v.y);
        }

        float inv = 1.0f / (float)(cnt > 0 ? cnt : 1);
        if (cnt == 0) { mx = 0.f; my = 0.f; }

        crow[lane]      = make_float2(sx * inv, sy * inv);  // mean: k in [0,64)
        crow[32 + lane] = make_float2(mx, my);              // max:  k in [64,128)
        __syncwarp();

        // projection: acc = (even-k partial, odd-k partial) per output j
        unsigned long long acc0 = 0ULL, acc1 = 0ULL;  // j = lane, j = lane+32
        #pragma unroll 16
        for (int kp = 0; kp < 64; kp++) {
            unsigned long long aa = Au[kp];             // broadcast (k=2kp,2kp+1)
            ffma2(acc0, aa, Wu[kp * 64 + lane]);
            ffma2(acc1, aa, Wu[kp * 64 + lane + 32]);
        }
        float e0, o0, e1, o1;
        unpack2(acc0, e0, o0);
        unpack2(acc1, e1, o1);
        out[(size_t)dom * 64 + lane]      = e0 + o0 + b0;
        out[(size_t)dom * 64 + lane + 32] = e1 + o1 + b1;
        __syncwarp();   // protect Csm row before next group's overwrite
    }
}

// ---------------------------------------------------------------- launch
extern "C" void kernel_launch(void* const* d_in, const int* in_sizes, int n_in,
                              void* d_out, int out_size) {
    const float* emb = nullptr;
    const void*  idx = nullptr;
    const float* W   = nullptr;
    const float* b   = nullptr;
    for (int i = 0; i < n_in; i++) {
        long long sz = in_sizes[i];
        if (sz == 268435456LL || sz == 1073741824LL)           emb = (const float*)d_in[i];
        else if (sz == 4194304LL || sz == 33554432LL
                                 || sz == 16777216LL)          idx = d_in[i];
        else if (sz == 8192LL || sz == 32768LL)                W   = (const float*)d_in[i];
        else if (sz == 64LL  || sz == 256LL)                   b   = (const float*)d_in[i];
    }
    if (!emb || !idx || !W || !b) {
        emb = (const float*)d_in[0];
        idx = d_in[1];
        if (n_in >= 5) { W = (const float*)d_in[3]; b = (const float*)d_in[4]; }
        else           { W = (const float*)d_in[2]; b = (const float*)d_in[3]; }
    }
    float* out = (float*)d_out;
    const int n = NPULSES;

    k_detect   <<<1, 1>>>((const unsigned int*)idx);
    k_zero     <<<NDOMS / 1024, 1024>>>();
    k_wt       <<<32, 256>>>(W);
    k_hist     <<<(n + 255) / 256, 256>>>(idx, n);
    k_scan1    <<<256, 1024>>>();
    k_scan2    <<<1, 256>>>();
    k_scan3    <<<256, 1024>>>();
    k_scatter  <<<(n + 255) / 256, 256>>>(idx, n);
    k_pool_gemm<<<PGRID, 256>>>(emb, b, out);
}

// round 7
// speedup vs baseline: 1.0742x; 1.0742x over previous
#include <cuda_runtime.h>
#include <cstdint>
#include <cfloat>

#define NDOMS   262144
#define NPULSES 4194304
#define EMBED   64

// ---- static scratch (no allocs allowed) ----
__device__ int   g_count [NDOMS];
__device__ int   g_offset[NDOMS];
__device__ int   g_cursor[NDOMS];
__device__ int   g_perm  [NPULSES];
__device__ int   g_bsum  [256];
__device__ int   g_is64;
// W k-paired for f32x2: Wu[kp*64 + j] = ( W[j][2kp], W[j][2kp+1] )
__device__ float g_wp[128 * 64];
__device__ float g_concat[(size_t)NDOMS * 128];   // [NDOMS][128] mean|max

// ---- f32x2 packed helpers ----
__device__ __forceinline__ void unpack2(unsigned long long u, float& x, float& y) {
    asm("mov.b64 {%0, %1}, %2;" : "=f"(x), "=f"(y) : "l"(u));
}
__device__ __forceinline__ void ffma2(unsigned long long& acc,
                                      unsigned long long a, unsigned long long b) {
    asm("fma.rn.f32x2 %0, %1, %2, %0;" : "+l"(acc) : "l"(a), "l"(b));
}

// ---------------------------------------------------------------- idx dtype probe
__global__ void k_detect(const unsigned int* __restrict__ idx32) {
    int is64 = 1;
    for (int i = 0; i < 128; i++)
        if (idx32[2 * i + 1] != 0u) { is64 = 0; break; }
    g_is64 = is64;
}

__device__ __forceinline__ int load_idx(const void* __restrict__ idx, int i) {
    if (g_is64) return (int)((const long long*)idx)[i];
    return ((const int*)idx)[i];
}

// ---------------------------------------------------------------- zero counts
__global__ void k_zero() {
    int i = blockIdx.x * 1024 + threadIdx.x;
    g_count[i] = 0;
}

// ---------------------------------------------------------------- W pair-repack
__global__ void k_wt(const float* __restrict__ W) {
    int s = blockIdx.x * 256 + threadIdx.x;      // 8192 threads
    int j = s >> 7, k = s & 127;
    g_wp[(k >> 1) * 128 + 2 * j + (k & 1)] = W[s];
}

// ---------------------------------------------------------------- histogram
__global__ void k_hist(const void* __restrict__ idx, int n) {
    int i = blockIdx.x * 256 + threadIdx.x;
    if (i < n) atomicAdd(&g_count[load_idx(idx, i)], 1);
}

// ---------------------------------------------------------------- scan (3 phases)
__global__ void k_scan1() {
    __shared__ int sh[1024];
    int t = threadIdx.x;
    int i = blockIdx.x * 1024 + t;
    int v = g_count[i];
    sh[t] = v;
    __syncthreads();
    for (int off = 1; off < 1024; off <<= 1) {
        int add = (t >= off) ? sh[t - off] : 0;
        __syncthreads();
        sh[t] += add;
        __syncthreads();
    }
    g_offset[i] = sh[t] - v;
    if (t == 1023) g_bsum[blockIdx.x] = sh[t];
}

__global__ void k_scan2() {
    __shared__ int sh[256];
    int t = threadIdx.x;
    int v = g_bsum[t];
    sh[t] = v;
    __syncthreads();
    for (int off = 1; off < 256; off <<= 1) {
        int add = (t >= off) ? sh[t - off] : 0;
        __syncthreads();
        sh[t] += add;
        __syncthreads();
    }
    g_bsum[t] = sh[t] - v;
}

__global__ void k_scan3() {
    int t = threadIdx.x;
    int i = blockIdx.x * 1024 + t;
    int o = g_offset[i] + g_bsum[blockIdx.x];
    g_offset[i] = o;
    g_cursor[i] = o;
}

// ---------------------------------------------------------------- scatter pulse ids
__global__ void k_scatter(const void* __restrict__ idx, int n) {
    int i = blockIdx.x * 256 + threadIdx.x;
    if (i < n) {
        int d   = load_idx(idx, i);
        int pos = atomicAdd(&g_cursor[d], 1);
        g_perm[pos] = i;
    }
}

// ---------------------------------------------------------------- pool (R5 proven)
__global__ void __launch_bounds__(256) k_pool(const float* __restrict__ emb) {
    int gw   = (blockIdx.x * blockDim.x + threadIdx.x) >> 5;
    int lane = threadIdx.x & 31;
    if (gw >= NDOMS) return;

    int start = g_offset[gw];
    int cnt   = g_count[gw];

    const float2* e2 = (const float2*)emb;
    float sx = 0.f, sy = 0.f;
    float mx = -FLT_MAX, my = -FLT_MAX;

    int i = 0;
    int p[8];
    if (cnt >= 8) {
        #pragma unroll
        for (int u = 0; u < 8; u++) p[u] = g_perm[start + u];
    }
    while (i + 8 <= cnt) {
        float2 v[8];
        #pragma unroll
        for (int u = 0; u < 8; u++)
            v[u] = e2[(size_t)p[u] * 32 + lane];
        i += 8;
        if (i + 8 <= cnt) {
            #pragma unroll
            for (int u = 0; u < 8; u++) p[u] = g_perm[start + i + u];
        }
        #pragma unroll
        for (int u = 0; u < 8; u++) {
            sx += v[u].x; sy += v[u].y;
            mx = fmaxf(mx, v[u].x); my = fmaxf(my, v[u].y);
        }
    }
    for (; i < cnt; i++) {
        int q = g_perm[start + i];
        float2 v = e2[(size_t)q * 32 + lane];
        sx += v.x; sy += v.y;
        mx = fmaxf(mx, v.x); my = fmaxf(my, v.y);
    }

    float inv = 1.0f / (float)(cnt > 0 ? cnt : 1);
    if (cnt == 0) { mx = 0.f; my = 0.f; }

    float2* crow = (float2*)(g_concat + (size_t)gw * 128);
    crow[lane]      = make_float2(sx * inv, sy * inv);   // mean cols [0,64)
    crow[32 + lane] = make_float2(mx, my);               // max  cols [64,128)
}

// ---------------------------------------------------------------- projection GEMM
// k-paired FFMA2: acc = (even-k partial, odd-k partial). Both operands are
// natural 64-bit loads -> ZERO packing MOVs.
// 32 dom-rows/tile, 128 threads, 4m x 4j per thread; persistent.
#define GEMM_BLOCKS 592   // 148 SMs * 4 (smem-limited)

__global__ void __launch_bounds__(128) k_gemm(const float* __restrict__ bias,
                                              float* __restrict__ out) {
    extern __shared__ float sm[];
    float* As = sm;                 // [32][128]  (ull view: [32][64] k-pairs)
    float* Bs = sm + 32 * 128;      // paired W   (ull view: [64 kp][64 j])

    int tid = threadIdx.x;

    // stage paired W once per block
    const float4* Wp4 = (const float4*)g_wp;
    float4* Bs4 = (float4*)Bs;
    #pragma unroll
    for (int i = 0; i < 16; i++)
        Bs4[tid + i * 128] = Wp4[tid + i * 128];

    int tj = tid & 15, tm = tid >> 4;
    int m0 = tm * 4, j0 = tj * 4;
    float4 bv4 = *(const float4*)&bias[j0];

    float4* As4 = (float4*)As;
    const unsigned long long* Asu = (const unsigned long long*)As;  // [m][kp]
    const unsigned long long* Bsu = (const unsigned long long*)Bs;  // [kp][j]

    for (int tile = blockIdx.x; tile < NDOMS / 32; tile += GEMM_BLOCKS) {
        __syncthreads();
        const float4* A4 = (const float4*)(g_concat + (size_t)tile * 32 * 128);
        #pragma unroll
        for (int i = 0; i < 8; i++)
            As4[tid + i * 128] = A4[tid + i * 128];
        __syncthreads();

        unsigned long long acc[4][4];
        #pragma unroll
        for (int i = 0; i < 4; i++)
            #pragma unroll
            for (int j = 0; j < 4; j++) acc[i][j] = 0ULL;

        #pragma unroll 8
        for (int kp = 0; kp < 64; kp += 2) {
            // A: one LDS.128 per m-row covers kp and kp+1 (broadcast over tj)
            unsigned long long a[4][2];
            #pragma unroll
            for (int m = 0; m < 4; m++) {
                float4 av = *(const float4*)&Asu[(m0 + m) * 64 + kp];
                a[m][0] = ((const unsigned long long*)&av)[0];
                a[m][1] = ((const unsigned long long*)&av)[1];
            }
            #pragma unroll
            for (int d = 0; d < 2; d++) {
                // B: 4 j-pairs = 2 LDS.128 (16 distinct 32B segs/warp, no conflict)
                float4 bv0 = *(const float4*)&Bsu[(kp + d) * 64 + j0];
                float4 bv1 = *(const float4*)&Bsu[(kp + d) * 64 + j0 + 2];
                unsigned long long b0 = ((const unsigned long long*)&bv0)[0];
                unsigned long long b1 = ((const unsigned long long*)&bv0)[1];
                unsigned long long b2 = ((const unsigned long long*)&bv1)[0];
                unsigned long long b3 = ((const unsigned long long*)&bv1)[1];
                #pragma unroll
                for (int m = 0; m < 4; m++) {
                    ffma2(acc[m][0], a[m][d], b0);
                    ffma2(acc[m][1], a[m][d], b1);
                    ffma2(acc[m][2], a[m][d], b2);
                    ffma2(acc[m][3], a[m][d], b3);
                }
            }
        }

        int dom0 = tile * 32;
        #pragma unroll
        for (int m = 0; m < 4; m++) {
            float r[4];
            #pragma unroll
            for (int j = 0; j < 4; j++) {
                float ev, od;
                unpack2(acc[m][j], ev, od);
                r[j] = ev + od;
            }
            float4 o;
            o.x = r[0] + bv4.x; o.y = r[1] + bv4.y;
            o.z = r[2] + bv4.z; o.w = r[3] + bv4.w;
            *(float4*)&out[(size_t)(dom0 + m0 + m) * 64 + j0] = o;
        }
    }
}

// ---------------------------------------------------------------- launch
extern "C" void kernel_launch(void* const* d_in, const int* in_sizes, int n_in,
                              void* d_out, int out_size) {
    const float* emb = nullptr;
    const void*  idx = nullptr;
    const float* W   = nullptr;
    const float* b   = nullptr;
    for (int i = 0; i < n_in; i++) {
        long long sz = in_sizes[i];
        if (sz == 268435456LL || sz == 1073741824LL)           emb = (const float*)d_in[i];
        else if (sz == 4194304LL || sz == 33554432LL
                                 || sz == 16777216LL)          idx = d_in[i];
        else if (sz == 8192LL || sz == 32768LL)                W   = (const float*)d_in[i];
        else if (sz == 64LL  || sz == 256LL)                   b   = (const float*)d_in[i];
    }
    if (!emb || !idx || !W || !b) {
        emb = (const float*)d_in[0];
        idx = d_in[1];
        if (n_in >= 5) { W = (const float*)d_in[3]; b = (const float*)d_in[4]; }
        else           { W = (const float*)d_in[2]; b = (const float*)d_in[3]; }
    }
    float* out = (float*)d_out;
    const int n = NPULSES;

    k_detect <<<1, 1>>>((const unsigned int*)idx);
    k_zero   <<<NDOMS / 1024, 1024>>>();
    k_wt     <<<32, 256>>>(W);
    k_hist   <<<(n + 255) / 256, 256>>>(idx, n);
    k_scan1  <<<256, 1024>>>();
    k_scan2  <<<1, 256>>>();
    k_scan3  <<<256, 1024>>>();
    k_scatter<<<(n + 255) / 256, 256>>>(idx, n);
    k_pool   <<<NDOMS / 8, 256>>>(emb);
    k_gemm   <<<GEMM_BLOCKS, 128, 49152>>>(b, out);
}

// round 8
// speedup vs baseline: 1.1533x; 1.0736x over previous
#include <cuda_runtime.h>
#include <cstdint>
#include <cfloat>

#define NDOMS   262144
#define NPULSES 4194304
#define EMBED   64

// ---- static scratch (no allocs allowed) ----
__device__ int   g_count [NDOMS];
__device__ int   g_offset[NDOMS];
__device__ int   g_cursor[NDOMS];
__device__ int   g_perm  [NPULSES];
__device__ int   g_bsum  [256];
__device__ int   g_is64;
__device__ float g_wt[128 * 64];   // W transposed: g_wt[k*64+j] = W[j][k]

// ---------------------------------------------------------------- idx dtype probe
// parallel: 32 lanes x 4 odd-words each; int64 values < 2^31 => all zero.
__global__ void k_detect(const unsigned int* __restrict__ idx32) {
    int lane = threadIdx.x;
    unsigned int v = idx32[2 * (lane * 4 + 0) + 1]
                   | idx32[2 * (lane * 4 + 1) + 1]
                   | idx32[2 * (lane * 4 + 2) + 1]
                   | idx32[2 * (lane * 4 + 3) + 1];
    unsigned int any = __ballot_sync(0xffffffffu, v != 0u);
    if (lane == 0) g_is64 = (any == 0u) ? 1 : 0;
}

__device__ __forceinline__ int load_idx(const void* __restrict__ idx, int i) {
    if (g_is64) return (int)((const long long*)idx)[i];
    return ((const int*)idx)[i];
}

// ---------------------------------------------------------------- zero counts
__global__ void k_zero() {
    int i = blockIdx.x * 1024 + threadIdx.x;
    g_count[i] = 0;
}

// ---------------------------------------------------------------- W transpose
__global__ void k_wt(const float* __restrict__ W) {
    int s = blockIdx.x * 256 + threadIdx.x;      // 8192 threads
    int j = s >> 7, k = s & 127;
    g_wt[k * 64 + j] = W[s];
}

// ---------------------------------------------------------------- histogram
__global__ void k_hist(const void* __restrict__ idx, int n) {
    int i = blockIdx.x * 256 + threadIdx.x;
    if (i < n) atomicAdd(&g_count[load_idx(idx, i)], 1);
}

// ---------------------------------------------------------------- scan (3 phases)
__global__ void k_scan1() {
    __shared__ int sh[1024];
    int t = threadIdx.x;
    int i = blockIdx.x * 1024 + t;
    int v = g_count[i];
    sh[t] = v;
    __syncthreads();
    for (int off = 1; off < 1024; off <<= 1) {
        int add = (t >= off) ? sh[t - off] : 0;
        __syncthreads();
        sh[t] += add;
        __syncthreads();
    }
    g_offset[i] = sh[t] - v;
    if (t == 1023) g_bsum[blockIdx.x] = sh[t];
}

__global__ void k_scan2() {
    __shared__ int sh[256];
    int t = threadIdx.x;
    int v = g_bsum[t];
    sh[t] = v;
    __syncthreads();
    for (int off = 1; off < 256; off <<= 1) {
        int add = (t >= off) ? sh[t - off] : 0;
        __syncthreads();
        sh[t] += add;
        __syncthreads();
    }
    g_bsum[t] = sh[t] - v;
}

__global__ void k_scan3() {
    int t = threadIdx.x;
    int i = blockIdx.x * 1024 + t;
    int o = g_offset[i] + g_bsum[blockIdx.x];
    g_offset[i] = o;
    g_cursor[i] = o;
}

// ---------------------------------------------------------------- scatter pulse ids
__global__ void k_scatter(const void* __restrict__ idx, int n) {
    int i = blockIdx.x * 256 + threadIdx.x;
    if (i < n) {
        int d   = load_idx(idx, i);
        int pos = atomicAdd(&g_cursor[d], 1);
        g_perm[pos] = i;
    }
}

// ---------------------------------------------------------------- fused pool+GEMM
// Persistent. Per group of 32 doms: 8 warps pool 4 doms each (R5-proven x8
// gather) into smem As[32][128]; __syncthreads; block GEMM (R4-proven scalar
// loop, W smem-resident once per block). No g_concat round-trip.
#define FGRID 592   // 148 SMs * 4 (48KB smem limited)

__global__ void __launch_bounds__(256) k_fused(const float* __restrict__ emb,
                                               const float* __restrict__ bias,
                                               float* __restrict__ out) {
    extern __shared__ float smx[];
    float* As = smx;              // [32][128] concat tile, 16KB
    float* Bs = smx + 32 * 128;   // [128][64]  Wt, 32KB

    int tid  = threadIdx.x;
    int wid  = tid >> 5;
    int lane = tid & 31;

    // stage Wt once per block
    const float4* Wt4 = (const float4*)g_wt;
    float4* Bs4 = (float4*)Bs;
    #pragma unroll
    for (int i = 0; i < 8; i++)
        Bs4[tid + i * 256] = Wt4[tid + i * 256];

    // gemm thread mapping: 2m x 4j micro-tile
    int tj = tid & 15, tm = tid >> 4;
    int m0 = tm * 2, j0 = tj * 4;
    float4 bv4 = *(const float4*)&bias[j0];

    const float2* e2 = (const float2*)emb;

    for (int grp = blockIdx.x; grp < NDOMS / 32; grp += FGRID) {
        // -------- pool phase: warp w -> doms grp*32 + w*4 + {0..3}
        __syncthreads();   // previous tile fully consumed
        #pragma unroll 1
        for (int d = 0; d < 4; d++) {
            int row   = wid * 4 + d;
            int dom   = grp * 32 + row;
            int start = g_offset[dom];
            int cnt   = g_count[dom];

            float sx = 0.f, sy = 0.f;
            float mx = -FLT_MAX, my = -FLT_MAX;

            int i = 0;
            int p[8];
            if (cnt >= 8) {
                #pragma unroll
                for (int u = 0; u < 8; u++) p[u] = g_perm[start + u];
            }
            while (i + 8 <= cnt) {
                float2 v[8];
                #pragma unroll
                for (int u = 0; u < 8; u++)
                    v[u] = e2[(size_t)p[u] * 32 + lane];
                i += 8;
                if (i + 8 <= cnt) {
                    #pragma unroll
                    for (int u = 0; u < 8; u++) p[u] = g_perm[start + i + u];
                }
                #pragma unroll
                for (int u = 0; u < 8; u++) {
                    sx += v[u].x; sy += v[u].y;
                    mx = fmaxf(mx, v[u].x); my = fmaxf(my, v[u].y);
                }
            }
            for (; i < cnt; i++) {
                int q = g_perm[start + i];
                float2 v = e2[(size_t)q * 32 + lane];
                sx += v.x; sy += v.y;
                mx = fmaxf(mx, v.x); my = fmaxf(my, v.y);
            }

            float inv = 1.0f / (float)(cnt > 0 ? cnt : 1);
            if (cnt == 0) { mx = 0.f; my = 0.f; }

            float2* crow = (float2*)&As[row * 128];
            crow[lane]      = make_float2(sx * inv, sy * inv);  // mean [0,64)
            crow[32 + lane] = make_float2(mx, my);              // max  [64,128)
        }
        __syncthreads();

        // -------- GEMM phase: C[32,64] = As[32,128] @ Bs[128,64] + bias
        float c[2][4];
        #pragma unroll
        for (int i = 0; i < 2; i++)
            #pragma unroll
            for (int j = 0; j < 4; j++) c[i][j] = 0.f;

        #pragma unroll 8
        for (int k = 0; k < 128; k++) {
            float a0 = As[(m0 + 0) * 128 + k];
            float a1 = As[(m0 + 1) * 128 + k];
            float4 bb = *(const float4*)&Bs[k * 64 + j0];
            c[0][0] = fmaf(a0, bb.x, c[0][0]); c[0][1] = fmaf(a0, bb.y, c[0][1]);
            c[0][2] = fmaf(a0, bb.z, c[0][2]); c[0][3] = fmaf(a0, bb.w, c[0][3]);
            c[1][0] = fmaf(a1, bb.x, c[1][0]); c[1][1] = fmaf(a1, bb.y, c[1][1]);
            c[1][2] = fmaf(a1, bb.z, c[1][2]); c[1][3] = fmaf(a1, bb.w, c[1][3]);
        }

        int dom0 = grp * 32;
        #pragma unroll
        for (int i = 0; i < 2; i++) {
            float4 r;
            r.x = c[i][0] + bv4.x; r.y = c[i][1] + bv4.y;
            r.z = c[i][2] + bv4.z; r.w = c[i][3] + bv4.w;
            *(float4*)&out[(size_t)(dom0 + m0 + i) * 64 + j0] = r;
        }
    }
}

// ---------------------------------------------------------------- launch
extern "C" void kernel_launch(void* const* d_in, const int* in_sizes, int n_in,
                              void* d_out, int out_size) {
    const float* emb = nullptr;
    const void*  idx = nullptr;
    const float* W   = nullptr;
    const float* b   = nullptr;
    for (int i = 0; i < n_in; i++) {
        long long sz = in_sizes[i];
        if (sz == 268435456LL || sz == 1073741824LL)           emb = (const float*)d_in[i];
        else if (sz == 4194304LL || sz == 33554432LL
                                 || sz == 16777216LL)          idx = d_in[i];
        else if (sz == 8192LL || sz == 32768LL)                W   = (const float*)d_in[i];
        else if (sz == 64LL  || sz == 256LL)                   b   = (const float*)d_in[i];
    }
    if (!emb || !idx || !W || !b) {
        emb = (const float*)d_in[0];
        idx = d_in[1];
        if (n_in >= 5) { W = (const float*)d_in[3]; b = (const float*)d_in[4]; }
        else           { W = (const float*)d_in[2]; b = (const float*)d_in[3]; }
    }
    float* out = (float*)d_out;
    const int n = NPULSES;

    k_detect <<<1, 32>>>((const unsigned int*)idx);
    k_zero   <<<NDOMS / 1024, 1024>>>();
    k_wt     <<<32, 256>>>(W);
    k_hist   <<<(n + 255) / 256, 256>>>(idx, n);
    k_scan1  <<<256, 1024>>>();
    k_scan2  <<<1, 256>>>();
    k_scan3  <<<256, 1024>>>();
    k_scatter<<<(n + 255) / 256, 256>>>(idx, n);
    k_fused  <<<FGRID, 256, 49152>>>(emb, b, out);
}

// round 9
// speedup vs baseline: 1.2278x; 1.0646x over previous
#include <cuda_runtime.h>
#include <cstdint>
#include <cfloat>

#define NDOMS   262144
#define NPULSES 4194304
#define EMBED   64

// ---- static scratch (no allocs allowed) ----
__device__ int   g_count [NDOMS];
__device__ int   g_offset[NDOMS];
__device__ int   g_cursor[NDOMS];
__device__ int   g_perm  [NPULSES];
__device__ int   g_bsum  [256];
__device__ int   g_is64;
__device__ float g_wt[128 * 64];   // W transposed: g_wt[k*64+j] = W[j][k]
__device__ float g_concat[(size_t)NDOMS * 128];   // [NDOMS][128] mean|max

// ---------------------------------------------------------------- idx dtype probe
// parallel: 32 lanes x 4 odd-words each; int64 values < 2^31 => all zero.
__global__ void k_detect(const unsigned int* __restrict__ idx32) {
    int lane = threadIdx.x;
    unsigned int v = idx32[2 * (lane * 4 + 0) + 1]
                   | idx32[2 * (lane * 4 + 1) + 1]
                   | idx32[2 * (lane * 4 + 2) + 1]
                   | idx32[2 * (lane * 4 + 3) + 1];
    unsigned int any = __ballot_sync(0xffffffffu, v != 0u);
    if (lane == 0) g_is64 = (any == 0u) ? 1 : 0;
}

__device__ __forceinline__ int load_idx(const void* __restrict__ idx, int i) {
    if (g_is64) return (int)((const long long*)idx)[i];
    return ((const int*)idx)[i];
}

// ---------------------------------------------------------------- zero counts
__global__ void k_zero() {
    int i = blockIdx.x * 1024 + threadIdx.x;     // 65536 threads, int4-wide
    ((int4*)g_count)[i] = make_int4(0, 0, 0, 0);
}

// ---------------------------------------------------------------- W transpose
__global__ void k_wt(const float* __restrict__ W) {
    int s = blockIdx.x * 256 + threadIdx.x;      // 8192 threads
    int j = s >> 7, k = s & 127;
    g_wt[k * 64 + j] = W[s];
}

// ---------------------------------------------------------------- histogram
__global__ void k_hist(const void* __restrict__ idx, int n) {
    int i = blockIdx.x * 256 + threadIdx.x;
    if (i < n) atomicAdd(&g_count[load_idx(idx, i)], 1);
}

// ---------------------------------------------------------------- scan (3 phases)
__global__ void k_scan1() {
    __shared__ int sh[1024];
    int t = threadIdx.x;
    int i = blockIdx.x * 1024 + t;
    int v = g_count[i];
    sh[t] = v;
    __syncthreads();
    for (int off = 1; off < 1024; off <<= 1) {
        int add = (t >= off) ? sh[t - off] : 0;
        __syncthreads();
        sh[t] += add;
        __syncthreads();
    }
    g_offset[i] = sh[t] - v;
    if (t == 1023) g_bsum[blockIdx.x] = sh[t];
}

__global__ void k_scan2() {
    __shared__ int sh[256];
    int t = threadIdx.x;
    int v = g_bsum[t];
    sh[t] = v;
    __syncthreads();
    for (int off = 1; off < 256; off <<= 1) {
        int add = (t >= off) ? sh[t - off] : 0;
        __syncthreads();
        sh[t] += add;
        __syncthreads();
    }
    g_bsum[t] = sh[t] - v;
}

__global__ void k_scan3() {
    int t = threadIdx.x;
    int i = blockIdx.x * 1024 + t;
    int o = g_offset[i] + g_bsum[blockIdx.x];
    g_offset[i] = o;
    g_cursor[i] = o;
}

// ---------------------------------------------------------------- scatter pulse ids
__global__ void k_scatter(const void* __restrict__ idx, int n) {
    int i = blockIdx.x * 256 + threadIdx.x;
    if (i < n) {
        int d   = load_idx(idx, i);
        int pos = atomicAdd(&g_cursor[d], 1);
        g_perm[pos] = i;
    }
}

// ---------------------------------------------------------------- pool: warp per DOM
// Full-MLP loop: ALWAYS 8 row loads in flight (tail uses clamped duplicate
// indices; accumulation predicated). Streaming loads bypass L1 fill.
__global__ void __launch_bounds__(256) k_pool(const float* __restrict__ emb) {
    int gw   = (blockIdx.x * blockDim.x + threadIdx.x) >> 5;
    int lane = threadIdx.x & 31;
    if (gw >= NDOMS) return;

    int start = g_offset[gw];
    int cnt   = g_count[gw];

    const float2* e2 = (const float2*)emb;
    float sx = 0.f, sy = 0.f;
    float mx = -FLT_MAX, my = -FLT_MAX;

    for (int i = 0; i < cnt; i += 8) {
        int m = cnt - i;                       // remaining (>0)
        int p[8];
        #pragma unroll
        for (int u = 0; u < 8; u++) {
            int uu = (u < m) ? u : (m - 1);    // clamp: dup loads are discarded
            p[u] = g_perm[start + i + uu];
        }
        float2 v[8];
        #pragma unroll
        for (int u = 0; u < 8; u++)            // 8 independent 256B row loads
            v[u] = __ldcs(&e2[(size_t)p[u] * 32 + lane]);
        #pragma unroll
        for (int u = 0; u < 8; u++) {
            if (u < m) {
                sx += v[u].x; sy += v[u].y;
                mx = fmaxf(mx, v[u].x); my = fmaxf(my, v[u].y);
            }
        }
    }

    float inv = 1.0f / (float)(cnt > 0 ? cnt : 1);
    if (cnt == 0) { mx = 0.f; my = 0.f; }

    float2* crow = (float2*)(g_concat + (size_t)gw * 128);
    crow[lane]      = make_float2(sx * inv, sy * inv);   // mean cols [0,64)
    crow[32 + lane] = make_float2(mx, my);               // max  cols [64,128)
}

// ---------------------------------------------------------------- projection GEMM
// persistent scalar (R4-proven): W smem-resident once per block.
// C[262144,64] = A[262144,128] @ Wt(128,64) + bias
#define GEMM_BLOCKS 592   // 148 SMs * 4 (smem-limited)

__global__ void __launch_bounds__(128) k_gemm(const float* __restrict__ bias,
                                              float* __restrict__ out) {
    extern __shared__ float sm[];
    float* As = sm;                 // [32][128]
    float* Bs = sm + 32 * 128;      // [128][64]

    int tid = threadIdx.x;

    const float4* Wt4 = (const float4*)g_wt;
    float4* Bs4 = (float4*)Bs;
    #pragma unroll
    for (int i = 0; i < 16; i++)
        Bs4[tid + i * 128] = Wt4[tid + i * 128];

    int tj = tid & 15, tm = tid >> 4;
    int m0 = tm * 4, j0 = tj * 4;
    float4 bv = *(const float4*)&bias[j0];

    float4* As4 = (float4*)As;

    for (int tile = blockIdx.x; tile < NDOMS / 32; tile += GEMM_BLOCKS) {
        __syncthreads();
        const float4* A4 = (const float4*)(g_concat + (size_t)tile * 32 * 128);
        #pragma unroll
        for (int i = 0; i < 8; i++)
            As4[tid + i * 128] = A4[tid + i * 128];
        __syncthreads();

        float c[4][4];
        #pragma unroll
        for (int i = 0; i < 4; i++)
            #pragma unroll
            for (int j = 0; j < 4; j++) c[i][j] = 0.f;

        #pragma unroll 8
        for (int k = 0; k < 128; k++) {
            float a0 = As[(m0 + 0) * 128 + k];
            float a1 = As[(m0 + 1) * 128 + k];
            float a2 = As[(m0 + 2) * 128 + k];
            float a3 = As[(m0 + 3) * 128 + k];
            float4 bb = *(const float4*)&Bs[k * 64 + j0];
            c[0][0] = fmaf(a0, bb.x, c[0][0]); c[0][1] = fmaf(a0, bb.y, c[0][1]);
            c[0][2] = fmaf(a0, bb.z, c[0][2]); c[0][3] = fmaf(a0, bb.w, c[0][3]);
            c[1][0] = fmaf(a1, bb.x, c[1][0]); c[1][1] = fmaf(a1, bb.y, c[1][1]);
            c[1][2] = fmaf(a1, bb.z, c[1][2]); c[1][3] = fmaf(a1, bb.w, c[1][3]);
            c[2][0] = fmaf(a2, bb.x, c[2][0]); c[2][1] = fmaf(a2, bb.y, c[2][1]);
            c[2][2] = fmaf(a2, bb.z, c[2][2]); c[2][3] = fmaf(a2, bb.w, c[2][3]);
            c[3][0] = fmaf(a3, bb.x, c[3][0]); c[3][1] = fmaf(a3, bb.y, c[3][1]);
            c[3][2] = fmaf(a3, bb.z, c[3][2]); c[3][3] = fmaf(a3, bb.w, c[3][3]);
        }

        int dom0 = tile * 32;
        #pragma unroll
        for (int i = 0; i < 4; i++) {
            float4 r;
            r.x = c[i][0] + bv.x; r.y = c[i][1] + bv.y;
            r.z = c[i][2] + bv.z; r.w = c[i][3] + bv.w;
            *(float4*)&out[(size_t)(dom0 + m0 + i) * 64 + j0] = r;
        }
    }
}

// ---------------------------------------------------------------- launch
extern "C" void kernel_launch(void* const* d_in, const int* in_sizes, int n_in,
                              void* d_out, int out_size) {
    const float* emb = nullptr;
    const void*  idx = nullptr;
    const float* W   = nullptr;
    const float* b   = nullptr;
    for (int i = 0; i < n_in; i++) {
        long long sz = in_sizes[i];
        if (sz == 268435456LL || sz == 1073741824LL)           emb = (const float*)d_in[i];
        else if (sz == 4194304LL || sz == 33554432LL
                                 || sz == 16777216LL)          idx = d_in[i];
        else if (sz == 8192LL || sz == 32768LL)                W   = (const float*)d_in[i];
        else if (sz == 64LL  || sz == 256LL)                   b   = (const float*)d_in[i];
    }
    if (!emb || !idx || !W || !b) {
        emb = (const float*)d_in[0];
        idx = d_in[1];
        if (n_in >= 5) { W = (const float*)d_in[3]; b = (const float*)d_in[4]; }
        else           { W = (const float*)d_in[2]; b = (const float*)d_in[3]; }
    }
    float* out = (float*)d_out;
    const int n = NPULSES;

    k_detect <<<1, 32>>>((const unsigned int*)idx);
    k_zero   <<<64, 1024>>>();
    k_wt     <<<32, 256>>>(W);
    k_hist   <<<(n + 255) / 256, 256>>>(idx, n);
    k_scan1  <<<256, 1024>>>();
    k_scan2  <<<1, 256>>>();
    k_scan3  <<<256, 1024>>>();
    k_scatter<<<(n + 255) / 256, 256>>>(idx, n);
    k_pool   <<<NDOMS / 8, 256>>>(emb);
    k_gemm   <<<GEMM_BLOCKS, 128, 49152>>>(b, out);
}

// round 10
// speedup vs baseline: 1.2403x; 1.0102x over previous
#include <cuda_runtime.h>
#include <cstdint>
#include <cfloat>

#define NDOMS   262144
#define NPULSES 4194304
#define EMBED   64

// ---- static scratch (no allocs allowed) ----
__device__ int   g_count [NDOMS];
__device__ int   g_offset[NDOMS];
__device__ int   g_cursor[NDOMS];
__device__ int   g_perm  [NPULSES];
__device__ int   g_is64;
__device__ unsigned long long g_scanpk[256];   // (state<<32)|value, state:1=agg,2=incl
__device__ float g_wt[128 * 64];               // W transposed: g_wt[k*64+j] = W[j][k]
__device__ float g_concat[(size_t)NDOMS * 128];

__device__ __forceinline__ int load_idx(const void* __restrict__ idx, int i) {
    if (g_is64) return (int)((const long long*)idx)[i];
    return ((const int*)idx)[i];
}

// ---------------------------------------------------------------- init (merged)
// blocks 0-63: zero g_count (int4-wide). block 64: detect dtype + reset scan
// state. blocks 65-72: W transpose.
__global__ void k_init(const unsigned int* __restrict__ idx32,
                       const float* __restrict__ W) {
    int b = blockIdx.x, t = threadIdx.x;
    if (b < 64) {
        ((int4*)g_count)[b * 1024 + t] = make_int4(0, 0, 0, 0);
    } else if (b == 64) {
        if (t < 32) {
            unsigned int v = idx32[2 * (t * 4 + 0) + 1]
                           | idx32[2 * (t * 4 + 1) + 1]
                           | idx32[2 * (t * 4 + 2) + 1]
                           | idx32[2 * (t * 4 + 3) + 1];
            unsigned int any = __ballot_sync(0xffffffffu, v != 0u);
            if (t == 0) g_is64 = (any == 0u) ? 1 : 0;
        } else if (t >= 32 && t < 288) {
            g_scanpk[t - 32] = 0ULL;
        }
    } else {
        int s = (b - 65) * 1024 + t;          // 8192 elems
        int j = s >> 7, k = s & 127;
        g_wt[k * 64 + j] = W[s];
    }
}

// ---------------------------------------------------------------- histogram
__global__ void k_hist(const void* __restrict__ idx, int n) {
    int i = blockIdx.x * 256 + threadIdx.x;
    if (i < n) atomicAdd(&g_count[load_idx(idx, i)], 1);
}

// ---------------------------------------------------------------- single-pass scan
// decoupled lookback; 256 blocks x 1024. Writes g_offset and g_cursor.
__global__ void k_scan() {
    __shared__ int sh[1024];
    __shared__ int s_prefix;
    int t = threadIdx.x, b = blockIdx.x;
    int i = b * 1024 + t;
    int v = g_count[i];
    sh[t] = v;
    __syncthreads();
    for (int off = 1; off < 1024; off <<= 1) {
        int add = (t >= off) ? sh[t - off] : 0;
        __syncthreads();
        sh[t] += add;
        __syncthreads();
    }
    if (t == 0) {
        int agg = sh[1023];
        int prefix = 0;
        if (b == 0) {
            atomicExch(&g_scanpk[0], (2ULL << 32) | (unsigned int)agg);
        } else {
            atomicExch(&g_scanpk[b], (1ULL << 32) | (unsigned int)agg);
            int j = b - 1;
            while (true) {
                unsigned long long pk = atomicAdd(&g_scanpk[j], 0ULL);
                unsigned int st = (unsigned int)(pk >> 32);
                if (st == 0u) continue;                 // not published yet
                prefix += (int)(unsigned int)pk;
                if (st == 2u) break;                    // inclusive: done
                j--;
            }
            atomicExch(&g_scanpk[b], (2ULL << 32) | (unsigned int)(prefix + agg));
        }
        s_prefix = prefix;
    }
    __syncthreads();
    int o = s_prefix + sh[t] - v;     // global exclusive prefix
    g_offset[i] = o;
    g_cursor[i] = o;
}

// ---------------------------------------------------------------- scatter pulse ids
__global__ void k_scatter(const void* __restrict__ idx, int n) {
    int i = blockIdx.x * 256 + threadIdx.x;
    if (i < n) {
        int d   = load_idx(idx, i);
        int pos = atomicAdd(&g_cursor[d], 1);
        g_perm[pos] = i;
    }
}

// ---------------------------------------------------------------- pool (R9 proven)
__global__ void __launch_bounds__(256) k_pool(const float* __restrict__ emb) {
    int gw   = (blockIdx.x * blockDim.x + threadIdx.x) >> 5;
    int lane = threadIdx.x & 31;
    if (gw >= NDOMS) return;

    int start = g_offset[gw];
    int cnt   = g_count[gw];

    const float2* e2 = (const float2*)emb;
    float sx = 0.f, sy = 0.f;
    float mx = -FLT_MAX, my = -FLT_MAX;

    for (int i = 0; i < cnt; i += 8) {
        int m = cnt - i;
        int p[8];
        #pragma unroll
        for (int u = 0; u < 8; u++) {
            int uu = (u < m) ? u : (m - 1);
            p[u] = g_perm[start + i + uu];
        }
        float2 v[8];
        #pragma unroll
        for (int u = 0; u < 8; u++)
            v[u] = __ldcs(&e2[(size_t)p[u] * 32 + lane]);
        #pragma unroll
        for (int u = 0; u < 8; u++) {
            if (u < m) {
                sx += v[u].x; sy += v[u].y;
                mx = fmaxf(mx, v[u].x); my = fmaxf(my, v[u].y);
            }
        }
    }

    float inv = 1.0f / (float)(cnt > 0 ? cnt : 1);
    if (cnt == 0) { mx = 0.f; my = 0.f; }

    float2* crow = (float2*)(g_concat + (size_t)gw * 128);
    crow[lane]      = make_float2(sx * inv, sy * inv);
    crow[32 + lane] = make_float2(mx, my);
}

// ---------------------------------------------------------------- projection GEMM
// persistent scalar + register prefetch of next A tile + k-pair A loads.
#define GEMM_BLOCKS 592
#define NTILES (NDOMS / 32)

__global__ void __launch_bounds__(128) k_gemm(const float* __restrict__ bias,
                                              float* __restrict__ out) {
    extern __shared__ float sm[];
    float* As = sm;                 // [32][128]
    float* Bs = sm + 32 * 128;      // [128][64]

    int tid = threadIdx.x;

    const float4* Wt4 = (const float4*)g_wt;
    float4* Bs4 = (float4*)Bs;
    #pragma unroll
    for (int i = 0; i < 16; i++)
        Bs4[tid + i * 128] = Wt4[tid + i * 128];

    int tj = tid & 15, tm = tid >> 4;
    int m0 = tm * 4, j0 = tj * 4;
    float4 bv = *(const float4*)&bias[j0];

    float4* As4 = (float4*)As;

    // prefetch first tile into registers
    float4 pre[8];
    int tile = blockIdx.x;
    if (tile < NTILES) {
        const float4* A4 = (const float4*)(g_concat + (size_t)tile * 32 * 128);
        #pragma unroll
        for (int i = 0; i < 8; i++) pre[i] = A4[tid + i * 128];
    }

    for (; tile < NTILES; tile += GEMM_BLOCKS) {
        __syncthreads();                       // previous tile consumed
        #pragma unroll
        for (int i = 0; i < 8; i++) As4[tid + i * 128] = pre[i];
        __syncthreads();

        int nxt = tile + GEMM_BLOCKS;
        if (nxt < NTILES) {                    // issue next-tile loads now;
            const float4* A4 = (const float4*)(g_concat + (size_t)nxt * 32 * 128);
            #pragma unroll                     // they overlap the compute below
            for (int i = 0; i < 8; i++) pre[i] = A4[tid + i * 128];
        }

        float c[4][4];
        #pragma unroll
        for (int i = 0; i < 4; i++)
            #pragma unroll
            for (int j = 0; j < 4; j++) c[i][j] = 0.f;

        #pragma unroll 8
        for (int k = 0; k < 128; k += 2) {
            float2 a0 = *(const float2*)&As[(m0 + 0) * 128 + k];
            float2 a1 = *(const float2*)&As[(m0 + 1) * 128 + k];
            float2 a2 = *(const float2*)&As[(m0 + 2) * 128 + k];
            float2 a3 = *(const float2*)&As[(m0 + 3) * 128 + k];
            float4 b0 = *(const float4*)&Bs[k * 64 + j0];
            float4 b1 = *(const float4*)&Bs[(k + 1) * 64 + j0];
            c[0][0] = fmaf(a0.x, b0.x, c[0][0]); c[0][1] = fmaf(a0.x, b0.y, c[0][1]);
            c[0][2] = fmaf(a0.x, b0.z, c[0][2]); c[0][3] = fmaf(a0.x, b0.w, c[0][3]);
            c[1][0] = fmaf(a1.x, b0.x, c[1][0]); c[1][1] = fmaf(a1.x, b0.y, c[1][1]);
            c[1][2] = fmaf(a1.x, b0.z, c[1][2]); c[1][3] = fmaf(a1.x, b0.w, c[1][3]);
            c[2][0] = fmaf(a2.x, b0.x, c[2][0]); c[2][1] = fmaf(a2.x, b0.y, c[2][1]);
            c[2][2] = fmaf(a2.x, b0.z, c[2][2]); c[2][3] = fmaf(a2.x, b0.w, c[2][3]);
            c[3][0] = fmaf(a3.x, b0.x, c[3][0]); c[3][1] = fmaf(a3.x, b0.y, c[3][1]);
            c[3][2] = fmaf(a3.x, b0.z, c[3][2]); c[3][3] = fmaf(a3.x, b0.w, c[3][3]);
            c[0][0] = fmaf(a0.y, b1.x, c[0][0]); c[0][1] = fmaf(a0.y, b1.y, c[0][1]);
            c[0][2] = fmaf(a0.y, b1.z, c[0][2]); c[0][3] = fmaf(a0.y, b1.w, c[0][3]);
            c[1][0] = fmaf(a1.y, b1.x, c[1][0]); c[1][1] = fmaf(a1.y, b1.y, c[1][1]);
            c[1][2] = fmaf(a1.y, b1.z, c[1][2]); c[1][3] = fmaf(a1.y, b1.w, c[1][3]);
            c[2][0] = fmaf(a2.y, b1.x, c[2][0]); c[2][1] = fmaf(a2.y, b1.y, c[2][1]);
            c[2][2] = fmaf(a2.y, b1.z, c[2][2]); c[2][3] = fmaf(a2.y, b1.w, c[2][3]);
            c[3][0] = fmaf(a3.y, b1.x, c[3][0]); c[3][1] = fmaf(a3.y, b1.y, c[3][1]);
            c[3][2] = fmaf(a3.y, b1.z, c[3][2]); c[3][3] = fmaf(a3.y, b1.w, c[3][3]);
        }

        int dom0 = tile * 32;
        #pragma unroll
        for (int i = 0; i < 4; i++) {
            float4 r;
            r.x = c[i][0] + bv.x; r.y = c[i][1] + bv.y;
            r.z = c[i][2] + bv.z; r.w = c[i][3] + bv.w;
            *(float4*)&out[(size_t)(dom0 + m0 + i) * 64 + j0] = r;
        }
    }
}

// ---------------------------------------------------------------- launch
extern "C" void kernel_launch(void* const* d_in, const int* in_sizes, int n_in,
                              void* d_out, int out_size) {
    const float* emb = nullptr;
    const void*  idx = nullptr;
    const float* W   = nullptr;
    const float* b   = nullptr;
    for (int i = 0; i < n_in; i++) {
        long long sz = in_sizes[i];
        if (sz == 268435456LL || sz == 1073741824LL)           emb = (const float*)d_in[i];
        else if (sz == 4194304LL || sz == 33554432LL
                                 || sz == 16777216LL)          idx = d_in[i];
        else if (sz == 8192LL || sz == 32768LL)                W   = (const float*)d_in[i];
        else if (sz == 64LL  || sz == 256LL)                   b   = (const float*)d_in[i];
    }
    if (!emb || !idx || !W || !b) {
        emb = (const float*)d_in[0];
        idx = d_in[1];
        if (n_in >= 5) { W = (const float*)d_in[3]; b = (const float*)d_in[4]; }
        else           { W = (const float*)d_in[2]; b = (const float*)d_in[3]; }
    }
    float* out = (float*)d_out;
    const int n = NPULSES;

    k_init   <<<73, 1024>>>((const unsigned int*)idx, W);
    k_hist   <<<(n + 255) / 256, 256>>>(idx, n);
    k_scan   <<<256, 1024>>>();
    k_scatter<<<(n + 255) / 256, 256>>>(idx, n);
    k_pool   <<<NDOMS / 8, 256>>>(emb);
    k_gemm   <<<GEMM_BLOCKS, 128, 49152>>>(b, out);
}